// round 16
// baseline (speedup 1.0000x reference)
#include <cuda_runtime.h>
#include <math.h>

#define BB 256
#define SS 365
#define FD 32
#define FS 27
#define HH 256
#define G3 768

#define OUT_OFF   0
#define HN_OFF    93440
#define CN_OFF    24014080

#define NCOL 96                    // 3 gates x 32 i per CTA
#define WSTRIDE_W 288              // w rows; quarter q at q*72 -> banks {0,8,16,24}
#define WSTRIDE_H 260              // h rows; 4-phase floor
#define HSM_OFF (NCOL * WSTRIDE_W)

typedef unsigned long long u64;

__device__ float g_xproj[(size_t)SS * G3 * BB];   // [s][col][b]
__device__ float g_h[2][BB * HH];                 // double-buffered hidden state
__device__ int   g_flag[128 * 32];                // flag (bt*8+ic) on its own 128B line

__device__ __forceinline__ u64 ffma2(u64 a, u64 b, u64 c) {
    u64 d;
    asm("fma.rn.f32x2 %0, %1, %2, %3;" : "=l"(d) : "l"(a), "l"(b), "l"(c));
    return d;
}
__device__ __forceinline__ u64 dup2(float x) {
    u64 r;
    asm("mov.b64 %0, {%1, %1};" : "=l"(r) : "f"(x));
    return r;
}
__device__ __forceinline__ float sigm_f(float x) {
    return __fdividef(1.0f, 1.0f + __expf(-x));
}
__device__ __forceinline__ float tanh_f(float x) {
    float t = __expf(2.0f * x);
    return 1.0f - __fdividef(2.0f, t + 1.0f);
}

__global__ void reset_kernel() {
    int idx = blockIdx.x * blockDim.x + threadIdx.x;
    if (idx < BB * HH) g_h[0][idx] = 0.0f;
    for (int f = idx; f < 128 * 32; f += gridDim.x * blockDim.x) g_flag[f] = 0;
}

__global__ void dummy_kernel() {}

// x_proj precompute with packed f32x2. grid: S blocks, 256 threads (thread = b).
__global__ void __launch_bounds__(256) xproj_kernel(const float* __restrict__ x_d,
                                                    const float* __restrict__ W_ih) {
    extern __shared__ float smf[];  // [pair][d*2+half], 384*64 floats
    const int s = blockIdx.x;
    const int tid = threadIdx.x;

    for (int idx = tid; idx < FD * G3; idx += 256) {
        int d = idx / G3, col = idx % G3;
        smf[(col >> 1) * 64 + d * 2 + (col & 1)] = W_ih[idx];
    }
    __syncthreads();

    u64 xp[FD];
    {
        const float4* xp4 = reinterpret_cast<const float4*>(x_d + ((size_t)tid * SS + s) * FD);
#pragma unroll
        for (int m = 0; m < 8; m++) {
            float4 v = xp4[m];
            xp[4*m]   = dup2(v.x);
            xp[4*m+1] = dup2(v.y);
            xp[4*m+2] = dup2(v.z);
            xp[4*m+3] = dup2(v.w);
        }
    }

    float* dst = g_xproj + (size_t)s * G3 * BB + tid;
    for (int p = 0; p < G3 / 2; p++) {
        u64 acc = 0ull;
        const ulonglong2* wp = reinterpret_cast<const ulonglong2*>(&smf[p * 64]);
#pragma unroll
        for (int dd = 0; dd < 16; dd++) {
            ulonglong2 q = wp[dd];
            acc = ffma2(xp[2*dd],     q.x, acc);
            acc = ffma2(xp[2*dd + 1], q.y, acc);
        }
        float2 pr = *reinterpret_cast<float2*>(&acc);
        dst[(size_t)(2*p)     * BB] = pr.x;
        dst[(size_t)(2*p + 1) * BB] = pr.y;
    }
}

// Persistent recurrence: grid 128 = 16 batch groups (16 b) x 8 CTAs (96 cols). 256 threads.
// warp w -> 4 i (w*4..w*4+3); lane: ks=lane>>3, bg=lane&7.
// Thread owns b = bt*16 + bg + 8*(ks&1), i pair = ic*32 + w*4 + 2*(ks>>1) + {0,1}.
__global__ void __launch_bounds__(256, 1) ealstm_kernel(const float* __restrict__ x_s,
                                                        const float* __restrict__ W_hh,
                                                        const float* __restrict__ W_sh,
                                                        const float* __restrict__ bias,
                                                        const float* __restrict__ bias_s,
                                                        float* __restrict__ d_out) {
    extern __shared__ float smem[];
    float* w_sm = smem;             // [96][288], k-gap swizzled
    float* h_sm = smem + HSM_OFF;   // [16][260]

    const int tid  = threadIdx.x;
    const int warp = tid >> 5;
    const int lane = tid & 31;
    const int ks   = lane >> 3;
    const int bg   = lane & 7;
    const int bt   = blockIdx.x >> 3;   // batch group (16 rows)
    const int ic   = blockIdx.x & 7;    // i-block of 32

    for (int idx = tid; idx < NCOL * HH; idx += 256) {
        int c = idx % NCOL, k = idx / NCOL;
        int gate = c >> 5, il = c & 31;
        int kp = k + ((k >> 6) << 3);
        w_sm[c * WSTRIDE_W + kp] = W_hh[k * G3 + gate * HH + ic * 32 + il];
    }

    const int b_glob = bt * 16 + bg + 8 * (ks & 1);
    const int i0     = ic * 32 + warp * 4 + 2 * (ks >> 1);

    float bf[2], bo[2], bgc[2], ig[2], creg[2];
#pragma unroll
    for (int il = 0; il < 2; il++) {
        int i = i0 + il;
        bf[il]  = bias[i];
        bo[il]  = bias[HH + i];
        bgc[il] = bias[2 * HH + i];
        float sum = bias_s[i];
        for (int d = 0; d < FS; d++)
            sum = fmaf(x_s[b_glob * FS + d], W_sh[d * HH + i], sum);
        ig[il] = 1.0f / (1.0f + expf(-sum));
        creg[il] = 0.0f;
    }
    __syncthreads();

    int hrow[2], wrow[12];
#pragma unroll
    for (int j = 0; j < 2; j++) hrow[j] = (bg + 8 * j) * WSTRIDE_H + ks * 64;
#pragma unroll
    for (int g = 0; g < 3; g++)
#pragma unroll
        for (int ci = 0; ci < 4; ci++)
            wrow[g * 4 + ci] = (g * 32 + warp * 4 + ci) * WSTRIDE_W + ks * 72;

    const int hl_row = tid >> 6;          // 0..3
    const int hl_k   = (tid & 63) * 4;

    int* my_flag = &g_flag[(bt * 8 + ic) * 32];
    const int* grp_flags = &g_flag[bt * 8 * 32];

    const int j_own = ks & 1;             // my row slot in acc[]
    const int sel   = (ks >> 1) & 1;      // my i-pair within each warp quad

    for (int s = 0; s < SS; s++) {
        // ---- wait FIRST (poll load at the head of the L1tex queue) ----
        if (s > 0) {
            const int* fp = grp_flags + (lane & 7) * 32;
            for (;;) {
                int v;
                asm volatile("ld.acquire.gpu.global.b32 %0, [%1];"
                             : "=r"(v) : "l"(fp) : "memory");
                if (__all_sync(0xffffffffu, v >= s)) break;
            }
        }

        // ---- load h tile [16 x 256] from g_h double buffer ----
        {
            const float* src_base = g_h[s & 1] + (size_t)bt * 16 * HH;
#pragma unroll
            for (int m = 0; m < 4; m++) {
                int rl = 4 * m + hl_row;
                float4 v = __ldcg(reinterpret_cast<const float4*>(src_base + rl * HH + hl_k));
                *reinterpret_cast<float4*>(&h_sm[rl * WSTRIDE_H + hl_k]) = v;
            }
        }

        // ---- prefetch x_proj additive terms (after h load, before sync) ----
        float xf[2], xo[2], xg[2];
        {
            const size_t xrow = (size_t)s * G3 * BB + b_glob;
#pragma unroll
            for (int il = 0; il < 2; il++) {
                int i = i0 + il;
                xf[il] = __ldg(&g_xproj[xrow + (size_t)i * BB]);
                xo[il] = __ldg(&g_xproj[xrow + (size_t)(HH + i) * BB]);
                xg[il] = __ldg(&g_xproj[xrow + (size_t)(2 * HH + i) * BB]);
            }
        }
        __syncthreads();

        // ---- packed f32x2 accumulation: 2 rows x 12 cols over this lane's k quarter ----
        u64 acc[2][12];
#pragma unroll
        for (int j = 0; j < 2; j++)
#pragma unroll
            for (int c = 0; c < 12; c++) acc[j][c] = 0ull;

#pragma unroll 4
        for (int kk = 0; kk < 16; kk++) {
            const int o = kk * 4;
            ulonglong2 h2[2];
#pragma unroll
            for (int j = 0; j < 2; j++)
                h2[j] = *reinterpret_cast<const ulonglong2*>(&h_sm[hrow[j] + o]);
#pragma unroll
            for (int c = 0; c < 12; c++) {
                ulonglong2 w2 = *reinterpret_cast<const ulonglong2*>(&w_sm[wrow[c] + o]);
#pragma unroll
                for (int j = 0; j < 2; j++) {
                    acc[j][c] = ffma2(h2[j].x, w2.x, acc[j][c]);
                    acc[j][c] = ffma2(h2[j].y, w2.y, acc[j][c]);
                }
            }
        }

        // ---- horizontal add (24 values) ----
        float hadd[2][12];
#pragma unroll
        for (int j = 0; j < 2; j++)
#pragma unroll
            for (int c = 0; c < 12; c++) {
                float2 p = *reinterpret_cast<float2*>(&acc[j][c]);
                hadd[j][c] = p.x + p.y;
            }

        // ---- select-before-exchange reduction ----
        // round 1 (xor 8, flips ks bit0 = row): keep my row j_own, send the other
        float r1[12];
#pragma unroll
        for (int c = 0; c < 12; c++) {
            float recv = __shfl_xor_sync(0xffffffffu, hadd[j_own ^ 1][c], 8);
            r1[c] = hadd[j_own][c] + recv;
        }
        // round 2 (xor 16, flips ks bit1 = i-pair): keep my pair cols, send the other
        float g6[6];
#pragma unroll
        for (int g = 0; g < 3; g++)
#pragma unroll
            for (int il = 0; il < 2; il++) {
                float recv = __shfl_xor_sync(0xffffffffu, r1[g * 4 + 2 * (sel ^ 1) + il], 16);
                g6[g * 2 + il] = r1[g * 4 + 2 * sel + il] + recv;
            }

        // ---- gate epilogue ----
        float hv[2], cv[2];
#pragma unroll
        for (int il = 0; il < 2; il++) {
            float f = g6[il]     + bf[il]  + xf[il];
            float o = g6[2 + il] + bo[il]  + xo[il];
            float g = g6[4 + il] + bgc[il] + xg[il];
            float cn = sigm_f(f) * creg[il] + ig[il] * tanh_f(g);
            float hn = sigm_f(o) * tanh_f(cn);
            creg[il] = cn;
            hv[il] = hn; cv[il] = cn;
        }

        // ---- publish h' (critical path) -> release flag -> cold d_out stores ----
        float2 h2v = make_float2(hv[0], hv[1]);
        float2 c2v = make_float2(cv[0], cv[1]);
        __stcg(reinterpret_cast<float2*>(&g_h[(s + 1) & 1][b_glob * HH + i0]), h2v);

        __syncthreads();   // all threads' h' stores ordered before tid0's release
        if (tid == 0) {
            asm volatile("st.release.gpu.global.b32 [%0], %1;"
                         :: "l"(my_flag), "r"(s + 1) : "memory");
        }

        size_t obase = ((size_t)b_glob * SS + s) * HH + i0;
        *reinterpret_cast<float2*>(&d_out[HN_OFF + obase]) = h2v;
        *reinterpret_cast<float2*>(&d_out[CN_OFF + obase]) = c2v;
    }
}

__global__ void __launch_bounds__(256) fc_kernel(const float* __restrict__ W_fc,
                                                 const float* __restrict__ b_fc,
                                                 float* __restrict__ d_out) {
    int gidx = blockIdx.x * 8 + (threadIdx.x >> 5);
    if (gidx >= BB * SS) return;
    int lane = threadIdx.x & 31;

    const float4* h4 = reinterpret_cast<const float4*>(d_out + HN_OFF + (size_t)gidx * HH) + lane * 2;
    const float4* w4 = reinterpret_cast<const float4*>(W_fc) + lane * 2;
    float4 a = h4[0], b = h4[1];
    float4 wa = w4[0], wb = w4[1];
    float sum = a.x * wa.x + a.y * wa.y + a.z * wa.z + a.w * wa.w
              + b.x * wb.x + b.y * wb.y + b.z * wb.z + b.w * wb.w;
#pragma unroll
    for (int off = 16; off > 0; off >>= 1)
        sum += __shfl_xor_sync(0xffffffffu, sum, off);
    if (lane == 0) d_out[OUT_OFF + gidx] = sum + b_fc[0];
}

extern "C" void kernel_launch(void* const* d_in, const int* in_sizes, int n_in,
                              void* d_out, int out_size) {
    const float* x_d    = (const float*)d_in[0];
    const float* x_s    = (const float*)d_in[1];
    const float* W_ih   = (const float*)d_in[2];
    const float* W_hh   = (const float*)d_in[3];
    const float* W_sh   = (const float*)d_in[4];
    const float* bias   = (const float*)d_in[5];
    const float* bias_s = (const float*)d_in[6];
    const float* W_fc   = (const float*)d_in[7];
    const float* b_fc   = (const float*)d_in[8];
    float* out = (float*)d_out;

    const int SMEM_X    = (G3 / 2) * 64 * sizeof(float);                          // 98304
    const int SMEM_MAIN = (NCOL * WSTRIDE_W + 16 * WSTRIDE_H) * sizeof(float);    // 127232

    cudaFuncSetAttribute(xproj_kernel, cudaFuncAttributeMaxDynamicSharedMemorySize, SMEM_X);
    cudaFuncSetAttribute(ealstm_kernel, cudaFuncAttributeMaxDynamicSharedMemorySize, SMEM_MAIN);

    reset_kernel<<<256, 256>>>();
    xproj_kernel<<<SS, 256, SMEM_X>>>(x_d, W_ih);
    dummy_kernel<<<1, 32>>>();
    ealstm_kernel<<<128, 256, SMEM_MAIN>>>(x_s, W_hh, W_sh, bias, bias_s, out);
    fc_kernel<<<(BB * SS + 7) / 8, 256>>>(W_fc, b_fc, out);
}

// round 17
// speedup vs baseline: 1.2739x; 1.2739x over previous
#include <cuda_runtime.h>
#include <math.h>

#define BB 256
#define SS 365
#define FD 32
#define FS 27
#define HH 256
#define G3 768

#define OUT_OFF   0
#define HN_OFF    93440
#define CN_OFF    24014080

#define NCOL 96                    // 3 gates x 32 i per CTA
#define WSTRIDE_W 288              // w rows; quarter q at q*72 -> banks {0,8,16,24}
#define WSTRIDE_H 260              // h rows; 4-phase floor
#define HSM_OFF (NCOL * WSTRIDE_W)

typedef unsigned long long u64;

// xproj layout: [s][pair][b][2]  (pair = col/2; packed float2 per (pair,b))
__device__ float g_xproj[(size_t)SS * (G3 / 2) * BB * 2];
__device__ float g_h[2][BB * HH];                 // double-buffered hidden state
__device__ int   g_flag[128 * 32];                // flag (bt*8+ic) on its own 128B line

__device__ __forceinline__ u64 ffma2(u64 a, u64 b, u64 c) {
    u64 d;
    asm("fma.rn.f32x2 %0, %1, %2, %3;" : "=l"(d) : "l"(a), "l"(b), "l"(c));
    return d;
}
__device__ __forceinline__ u64 dup2(float x) {
    u64 r;
    asm("mov.b64 %0, {%1, %1};" : "=l"(r) : "f"(x));
    return r;
}
__device__ __forceinline__ float sigm_f(float x) {
    return __fdividef(1.0f, 1.0f + __expf(-x));
}
__device__ __forceinline__ float tanh_f(float x) {
    float t = __expf(2.0f * x);
    return 1.0f - __fdividef(2.0f, t + 1.0f);
}

__global__ void reset_kernel() {
    int idx = blockIdx.x * blockDim.x + threadIdx.x;
    if (idx < BB * HH) g_h[0][idx] = 0.0f;
    for (int f = idx; f < 128 * 32; f += gridDim.x * blockDim.x) g_flag[f] = 0;
}

// x_proj precompute with packed f32x2. grid: S blocks, 256 threads (thread = b).
__global__ void __launch_bounds__(256) xproj_kernel(const float* __restrict__ x_d,
                                                    const float* __restrict__ W_ih) {
    extern __shared__ float smf[];  // [pair][d*2+half], 384*64 floats
    const int s = blockIdx.x;
    const int tid = threadIdx.x;

    for (int idx = tid; idx < FD * G3; idx += 256) {
        int d = idx / G3, col = idx % G3;
        smf[(col >> 1) * 64 + d * 2 + (col & 1)] = W_ih[idx];
    }
    __syncthreads();

    u64 xp[FD];
    {
        const float4* xp4 = reinterpret_cast<const float4*>(x_d + ((size_t)tid * SS + s) * FD);
#pragma unroll
        for (int m = 0; m < 8; m++) {
            float4 v = xp4[m];
            xp[4*m]   = dup2(v.x);
            xp[4*m+1] = dup2(v.y);
            xp[4*m+2] = dup2(v.z);
            xp[4*m+3] = dup2(v.w);
        }
    }

    // dst: [s][pair][b][2] -> one float2 store per pair
    float* dst = g_xproj + (size_t)s * (G3 / 2) * BB * 2 + tid * 2;
    for (int p = 0; p < G3 / 2; p++) {
        u64 acc = 0ull;
        const ulonglong2* wp = reinterpret_cast<const ulonglong2*>(&smf[p * 64]);
#pragma unroll
        for (int dd = 0; dd < 16; dd++) {
            ulonglong2 q = wp[dd];
            acc = ffma2(xp[2*dd],     q.x, acc);
            acc = ffma2(xp[2*dd + 1], q.y, acc);
        }
        *reinterpret_cast<float2*>(&dst[(size_t)p * BB * 2]) =
            *reinterpret_cast<float2*>(&acc);
    }
}

// Persistent recurrence: grid 128 = 16 batch groups (16 b) x 8 CTAs (96 cols). 256 threads.
// warp w -> 4 i (w*4..w*4+3); lane: ks=lane>>3, bg=lane&7.
// Thread owns b = bt*16 + bg + 8*(ks&1), i pair = ic*32 + w*4 + 2*(ks>>1) + {0,1}.
__global__ void __launch_bounds__(256, 1) ealstm_kernel(const float* __restrict__ x_s,
                                                        const float* __restrict__ W_hh,
                                                        const float* __restrict__ W_sh,
                                                        const float* __restrict__ bias,
                                                        const float* __restrict__ bias_s,
                                                        float* __restrict__ d_out) {
    extern __shared__ float smem[];
    float* w_sm = smem;             // [96][288], k-gap swizzled
    float* h_sm = smem + HSM_OFF;   // [16][260]

    const int tid  = threadIdx.x;
    const int warp = tid >> 5;
    const int lane = tid & 31;
    const int ks   = lane >> 3;
    const int bg   = lane & 7;
    const int bt   = blockIdx.x >> 3;   // batch group (16 rows)
    const int ic   = blockIdx.x & 7;    // i-block of 32

    for (int idx = tid; idx < NCOL * HH; idx += 256) {
        int c = idx % NCOL, k = idx / NCOL;
        int gate = c >> 5, il = c & 31;
        int kp = k + ((k >> 6) << 3);
        w_sm[c * WSTRIDE_W + kp] = W_hh[k * G3 + gate * HH + ic * 32 + il];
    }

    const int b_glob = bt * 16 + bg + 8 * (ks & 1);
    const int i0     = ic * 32 + warp * 4 + 2 * (ks >> 1);   // always even

    float bf[2], bo[2], bgc[2], ig[2], creg[2];
#pragma unroll
    for (int il = 0; il < 2; il++) {
        int i = i0 + il;
        bf[il]  = bias[i];
        bo[il]  = bias[HH + i];
        bgc[il] = bias[2 * HH + i];
        float sum = bias_s[i];
        for (int d = 0; d < FS; d++)
            sum = fmaf(x_s[b_glob * FS + d], W_sh[d * HH + i], sum);
        ig[il] = 1.0f / (1.0f + expf(-sum));
        creg[il] = 0.0f;
    }
    __syncthreads();

    int hrow[2], wrow[12];
#pragma unroll
    for (int j = 0; j < 2; j++) hrow[j] = (bg + 8 * j) * WSTRIDE_H + ks * 64;
#pragma unroll
    for (int g = 0; g < 3; g++)
#pragma unroll
        for (int ci = 0; ci < 4; ci++)
            wrow[g * 4 + ci] = (g * 32 + warp * 4 + ci) * WSTRIDE_W + ks * 72;

    const int hl_row = tid >> 6;          // 0..3
    const int hl_k   = (tid & 63) * 4;

    int* my_flag = &g_flag[(bt * 8 + ic) * 32];
    const int* grp_flags = &g_flag[bt * 8 * 32];

    // pair indices for the packed xproj layout
    const int pf = i0 >> 1;               // forget-gate pair
    const int po = pf + (HH >> 1);        // output-gate pair (+128)
    const int pg = pf + HH;               // cell-gate pair  (+256)

    for (int s = 0; s < SS; s++) {
        // ---- wait FIRST (poll load at the head of the L1tex queue) ----
        if (s > 0) {
            const int* fp = grp_flags + (lane & 7) * 32;
            for (;;) {
                int v;
                asm volatile("ld.acquire.gpu.global.b32 %0, [%1];"
                             : "=r"(v) : "l"(fp) : "memory");
                if (__all_sync(0xffffffffu, v >= s)) break;
            }
        }

        // ---- load h tile [16 x 256] from g_h double buffer ----
        {
            const float* src_base = g_h[s & 1] + (size_t)bt * 16 * HH;
#pragma unroll
            for (int m = 0; m < 4; m++) {
                int rl = 4 * m + hl_row;
                float4 v = __ldcg(reinterpret_cast<const float4*>(src_base + rl * HH + hl_k));
                *reinterpret_cast<float4*>(&h_sm[rl * WSTRIDE_H + hl_k]) = v;
            }
        }

        // ---- prefetch x_proj additive terms: 3 float2 loads (packed pairs) ----
        float2 xf2, xo2, xg2;
        {
            const float* xrow = g_xproj + (size_t)s * (G3 / 2) * BB * 2 + b_glob * 2;
            xf2 = __ldg(reinterpret_cast<const float2*>(&xrow[(size_t)pf * BB * 2]));
            xo2 = __ldg(reinterpret_cast<const float2*>(&xrow[(size_t)po * BB * 2]));
            xg2 = __ldg(reinterpret_cast<const float2*>(&xrow[(size_t)pg * BB * 2]));
        }
        __syncthreads();

        // ---- packed f32x2 accumulation: 2 rows x 12 cols over this lane's k quarter ----
        u64 acc[2][12];
#pragma unroll
        for (int j = 0; j < 2; j++)
#pragma unroll
            for (int c = 0; c < 12; c++) acc[j][c] = 0ull;

#pragma unroll 4
        for (int kk = 0; kk < 16; kk++) {
            const int o = kk * 4;
            ulonglong2 h2[2];
#pragma unroll
            for (int j = 0; j < 2; j++)
                h2[j] = *reinterpret_cast<const ulonglong2*>(&h_sm[hrow[j] + o]);
#pragma unroll
            for (int c = 0; c < 12; c++) {
                ulonglong2 w2 = *reinterpret_cast<const ulonglong2*>(&w_sm[wrow[c] + o]);
#pragma unroll
                for (int j = 0; j < 2; j++) {
                    acc[j][c] = ffma2(h2[j].x, w2.x, acc[j][c]);
                    acc[j][c] = ffma2(h2[j].y, w2.y, acc[j][c]);
                }
            }
        }

        // ---- horizontal add + full butterfly reduce (R11 form: uniform code) ----
        float accs[2][12];
#pragma unroll
        for (int j = 0; j < 2; j++)
#pragma unroll
            for (int c = 0; c < 12; c++) {
                float2 p = *reinterpret_cast<float2*>(&acc[j][c]);
                float v = p.x + p.y;
                v += __shfl_xor_sync(0xffffffffu, v, 8);
                v += __shfl_xor_sync(0xffffffffu, v, 16);
                accs[j][c] = v;
            }

        // ---- select this thread's 6 gate values (uniform ternaries) ----
        float g6[6];
#pragma unroll
        for (int g = 0; g < 3; g++)
#pragma unroll
            for (int il = 0; il < 2; il++) {
                float va = (ks & 2) ? accs[0][g*4 + 2 + il] : accs[0][g*4 + il];
                float vb = (ks & 2) ? accs[1][g*4 + 2 + il] : accs[1][g*4 + il];
                g6[g * 2 + il] = (ks & 1) ? vb : va;
            }

        // ---- gate epilogue ----
        float xf[2] = {xf2.x, xf2.y}, xo[2] = {xo2.x, xo2.y}, xg[2] = {xg2.x, xg2.y};
        float hv[2], cv[2];
#pragma unroll
        for (int il = 0; il < 2; il++) {
            float f = g6[il]     + bf[il]  + xf[il];
            float o = g6[2 + il] + bo[il]  + xo[il];
            float g = g6[4 + il] + bgc[il] + xg[il];
            float cn = sigm_f(f) * creg[il] + ig[il] * tanh_f(g);
            float hn = sigm_f(o) * tanh_f(cn);
            creg[il] = cn;
            hv[il] = hn; cv[il] = cn;
        }

        // ---- publish h' (critical path) -> release flag -> cold d_out stores ----
        float2 h2v = make_float2(hv[0], hv[1]);
        float2 c2v = make_float2(cv[0], cv[1]);
        __stcg(reinterpret_cast<float2*>(&g_h[(s + 1) & 1][b_glob * HH + i0]), h2v);

        __syncthreads();   // all threads' h' stores ordered before tid0's release
        if (tid == 0) {
            asm volatile("st.release.gpu.global.b32 [%0], %1;"
                         :: "l"(my_flag), "r"(s + 1) : "memory");
        }

        size_t obase = ((size_t)b_glob * SS + s) * HH + i0;
        *reinterpret_cast<float2*>(&d_out[HN_OFF + obase]) = h2v;
        *reinterpret_cast<float2*>(&d_out[CN_OFF + obase]) = c2v;
    }
}

__global__ void __launch_bounds__(256) fc_kernel(const float* __restrict__ W_fc,
                                                 const float* __restrict__ b_fc,
                                                 float* __restrict__ d_out) {
    int gidx = blockIdx.x * 8 + (threadIdx.x >> 5);
    if (gidx >= BB * SS) return;
    int lane = threadIdx.x & 31;

    const float4* h4 = reinterpret_cast<const float4*>(d_out + HN_OFF + (size_t)gidx * HH) + lane * 2;
    const float4* w4 = reinterpret_cast<const float4*>(W_fc) + lane * 2;
    float4 a = h4[0], b = h4[1];
    float4 wa = w4[0], wb = w4[1];
    float sum = a.x * wa.x + a.y * wa.y + a.z * wa.z + a.w * wa.w
              + b.x * wb.x + b.y * wb.y + b.z * wb.z + b.w * wb.w;
#pragma unroll
    for (int off = 16; off > 0; off >>= 1)
        sum += __shfl_xor_sync(0xffffffffu, sum, off);
    if (lane == 0) d_out[OUT_OFF + gidx] = sum + b_fc[0];
}

extern "C" void kernel_launch(void* const* d_in, const int* in_sizes, int n_in,
                              void* d_out, int out_size) {
    const float* x_d    = (const float*)d_in[0];
    const float* x_s    = (const float*)d_in[1];
    const float* W_ih   = (const float*)d_in[2];
    const float* W_hh   = (const float*)d_in[3];
    const float* W_sh   = (const float*)d_in[4];
    const float* bias   = (const float*)d_in[5];
    const float* bias_s = (const float*)d_in[6];
    const float* W_fc   = (const float*)d_in[7];
    const float* b_fc   = (const float*)d_in[8];
    float* out = (float*)d_out;

    const int SMEM_X    = (G3 / 2) * 64 * sizeof(float);                          // 98304
    const int SMEM_MAIN = (NCOL * WSTRIDE_W + 16 * WSTRIDE_H) * sizeof(float);    // 127232

    cudaFuncSetAttribute(xproj_kernel, cudaFuncAttributeMaxDynamicSharedMemorySize, SMEM_X);
    cudaFuncSetAttribute(ealstm_kernel, cudaFuncAttributeMaxDynamicSharedMemorySize, SMEM_MAIN);

    reset_kernel<<<256, 256>>>();
    xproj_kernel<<<SS, 256, SMEM_X>>>(x_d, W_ih);
    ealstm_kernel<<<128, 256, SMEM_MAIN>>>(x_s, W_hh, W_sh, bias, bias_s, out);
    fc_kernel<<<(BB * SS + 7) / 8, 256>>>(W_fc, b_fc, out);
}